// round 6
// baseline (speedup 1.0000x reference)
#include <cuda_runtime.h>
#include <cstdint>

typedef unsigned long long ull;
typedef unsigned int uint;

__device__ __forceinline__ ull pack2(float lo, float hi) {
    ull r; asm("mov.b64 %0, {%1, %2};" : "=l"(r) : "f"(lo), "f"(hi)); return r;
}
__device__ __forceinline__ void fma2(ull& acc, ull a, ull b) {
    asm("fma.rn.f32x2 %0, %1, %2, %0;" : "+l"(acc) : "l"(a), "l"(b));
}
__device__ __forceinline__ float2 unpack2(ull v) {
    float2 r; asm("mov.b64 {%0, %1}, %2;" : "=f"(r.x), "=f"(r.y) : "l"(v)); return r;
}
__device__ __forceinline__ float sigmoidf(float x) {
    return __fdividef(1.0f, 1.0f + __expf(-x));
}

// ---------------- xg kernel tiles (unchanged, validated R5) ----------------
template <int SA, int SB, int HALF>
__device__ __forceinline__ void mm84(const float* __restrict__ A,
                                     const float* __restrict__ B,
                                     int m0, int n0, ull acc[8][2]) {
#pragma unroll 8
    for (int k = 0; k < 64; ++k) {
        float4 a0 = *(const float4*)(A + k * SA + m0);
        float4 a1 = *(const float4*)(A + k * SA + m0 + HALF);
        float4 bv = *(const float4*)(B + k * SB + n0);
        ull b01 = pack2(bv.x, bv.y), b23 = pack2(bv.z, bv.w);
        ull a;
        a = pack2(a0.x, a0.x); fma2(acc[0][0], a, b01); fma2(acc[0][1], a, b23);
        a = pack2(a0.y, a0.y); fma2(acc[1][0], a, b01); fma2(acc[1][1], a, b23);
        a = pack2(a0.z, a0.z); fma2(acc[2][0], a, b01); fma2(acc[2][1], a, b23);
        a = pack2(a0.w, a0.w); fma2(acc[3][0], a, b01); fma2(acc[3][1], a, b23);
        a = pack2(a1.x, a1.x); fma2(acc[4][0], a, b01); fma2(acc[4][1], a, b23);
        a = pack2(a1.y, a1.y); fma2(acc[5][0], a, b01); fma2(acc[5][1], a, b23);
        a = pack2(a1.z, a1.z); fma2(acc[6][0], a, b01); fma2(acc[6][1], a, b23);
        a = pack2(a1.w, a1.w); fma2(acc[7][0], a, b01); fma2(acc[7][1], a, b23);
    }
}
__device__ __forceinline__ void zero8(ull acc[8][2]) {
#pragma unroll
    for (int r = 0; r < 8; ++r) { acc[r][0] = pack2(0.f,0.f); acc[r][1] = pack2(0.f,0.f); }
}

// mov-free 8x2 tile for rec: A loaded as b64 pairs (m contiguous),
// B loaded as pre-duplicated b64 pairs. acc[2p+q] = (C[m][nq], C[m+1][nq]),
// p over {m0,m0+2, strip+m0, strip+m0+2}.
template <int SA, int SB>
__device__ __forceinline__ void mm82(const float* __restrict__ A,
                                     const float* __restrict__ Bd,
                                     int m0, int strip, int doff, ull acc[8]) {
#pragma unroll 8
    for (int k = 0; k < 64; ++k) {
        ulonglong2 a01 = *(const ulonglong2*)(A + k * SA + m0);
        ulonglong2 a23 = *(const ulonglong2*)(A + k * SA + m0 + strip);
        ulonglong2 bb  = *(const ulonglong2*)(Bd + k * SB + doff);
        fma2(acc[0], a01.x, bb.x); fma2(acc[1], a01.x, bb.y);
        fma2(acc[2], a01.y, bb.x); fma2(acc[3], a01.y, bb.y);
        fma2(acc[4], a23.x, bb.x); fma2(acc[5], a23.x, bb.y);
        fma2(acc[6], a23.y, bb.x); fma2(acc[7], a23.y, bb.y);
    }
}

__device__ __forceinline__ void st_cluster_f32(uint32_t laddr, uint peer, float v) {
    uint32_t raddr;
    asm("mapa.shared::cluster.u32 %0, %1, %2;" : "=r"(raddr) : "r"(laddr), "r"(peer));
    asm volatile("st.shared::cluster.b32 [%0], %1;"
                 :: "r"(raddr), "r"(__float_as_uint(v)) : "memory");
}

// xg scratch: [l][g][n][a][b]  (384 MB device .bss)
__device__ float g_xg[(size_t)3 * 128 * 64 * 64 * 64];

// ============================================================================
// Phase 1 (unchanged from R5 — at its fp32x2 floor)
// ============================================================================
#define XS 68

__global__ void __launch_bounds__(256, 2)
xg_kernel(const float* __restrict__ inputs,
          const float* __restrict__ Ww1,
          const float* __restrict__ Ww2) {
    extern __shared__ float sm[];
    float* xs  = sm;
    float* w1T = sm + 2 * 64 * XS;
    float* w2T = w1T + 64 * XS;
    float* tmp = w2T + 64 * XS;

    const int lp = blockIdx.x, n = blockIdx.y;
    const int tid = threadIdx.x;
    const int half = tid >> 7, ht = tid & 127;
    const int m0 = (ht & 7) * 4, n0 = (ht >> 3) * 4;
    const int l = lp * 2 + half;

    float* xsb  = xs  + half * (64 * XS);
    float* tmpb = tmp + half * (64 * XS);

    const float* xsrc = inputs + ((size_t)n * 128 + l) * 4096;
    for (int e = ht; e < 1024; e += 128) {
        int i = e >> 4, j4 = (e & 15) * 4;
        *(float4*)(xsb + i * XS + j4) = *(const float4*)(xsrc + i * 64 + j4);
    }

    for (int g = 0; g < 3; ++g) {
        __syncthreads();
        for (int e = tid; e < 4096; e += 256) {
            int r = e >> 6, cc = e & 63;
            w1T[cc * XS + r] = Ww1[g * 4096 + e];
            w2T[cc * XS + r] = Ww2[g * 4096 + e];
        }
        __syncthreads();

        ull acc[8][2];
        zero8(acc);
        mm84<XS, XS, 32>(xsb, w1T, m0, n0, acc);
#pragma unroll
        for (int r = 0; r < 4; ++r) {
            float2 lo = unpack2(acc[r][0]),   hi = unpack2(acc[r][1]);
            float2 lo2 = unpack2(acc[4+r][0]), hi2 = unpack2(acc[4+r][1]);
            *(float4*)(tmpb + (m0 + r) * XS + n0) = make_float4(lo.x, lo.y, hi.x, hi.y);
            *(float4*)(tmpb + (32 + m0 + r) * XS + n0) = make_float4(lo2.x, lo2.y, hi2.x, hi2.y);
        }
        asm volatile("bar.sync %0, 128;" :: "r"(half + 1) : "memory");

        zero8(acc);
        mm84<XS, XS, 32>(tmpb, w2T, m0, n0, acc);
        float* dst = g_xg + ((size_t)(l * 3 + g) * 64 + n) * 4096;
#pragma unroll
        for (int r = 0; r < 4; ++r) {
            float2 lo = unpack2(acc[r][0]),   hi = unpack2(acc[r][1]);
            float2 lo2 = unpack2(acc[4+r][0]), hi2 = unpack2(acc[4+r][1]);
            *(float4*)(dst + (m0 + r) * 64 + n0) = make_float4(lo.x, lo.y, hi.x, hi.y);
            *(float4*)(dst + (32 + m0 + r) * 64 + n0) = make_float4(lo2.x, lo2.y, hi2.x, hi2.y);
        }
    }
}

// ============================================================================
// Phase 2: recurrence, mov-free fp32x2. Cluster-2, 384 threads = 3 gates x 128.
// stage1: tmp[j][a_l] = sum_i h[i][j]  * Wu1dup[i][a]   (m=j pairs, n=a dup)
// stage2: hg[a_l][b]  = sum_j tmp[j][a]* Wu2dup[j][b]   (m=a pairs, n=b dup)
// ============================================================================
#define HBX 68
#define TPX 36

__global__ void __launch_bounds__(384, 1) __cluster_dims__(2, 1, 1)
rec_kernel(const float* __restrict__ Wu1,
           const float* __restrict__ Wu2,
           float* __restrict__ out) {
    extern __shared__ float sm[];
    float* hbuf0 = sm;                 // [64][68] = 4352
    float* hbuf1 = sm + 4352;
    float* w1D   = sm + 8704;          // [3][64][64]  dup pairs over a_l
    float* w2D   = sm + 20992;         // [3][64][128] dup pairs over b
    float* tmpT  = sm + 45568;         // [3][64][36]
    float* buf   = sm + 52480;         // [2][16][128] SoA (z, r)

    const int bid  = blockIdx.x;
    const int n    = bid >> 1;
    const int rank = bid & 1;
    const int tid  = threadIdx.x;
    const int g    = tid >> 7;         // gate 0..2
    const int gt   = tid & 127;
    const int t1 = gt & 7, s1 = gt >> 3;   // stage1: m0=4*t1, dup off 4*s1
    const int t2 = gt & 3, s2 = gt >> 2;   // stage2: m0=4*t2, dup off 4*s2

    // ---- one-time staging: duplicated weights ----
    for (int gg = 0; gg < 3; ++gg) {
        for (int e = tid; e < 2048; e += 384) {
            int al = e >> 6, i = e & 63;
            float v = Wu1[gg * 4096 + (32 * rank + al) * 64 + i];
            w1D[gg * 4096 + i * 64 + 2 * al]     = v;
            w1D[gg * 4096 + i * 64 + 2 * al + 1] = v;
        }
        for (int e = tid; e < 4096; e += 384) {
            int b = e >> 6, j = e & 63;
            float v = Wu2[gg * 4096 + b * 64 + j];
            w2D[gg * 8192 + j * 128 + 2 * b]     = v;
            w2D[gg * 8192 + j * 128 + 2 * b + 1] = v;
        }
    }
    for (int e = tid; e < 8704; e += 384) sm[e] = 0.f;   // both h buffers

    float cst[16];
#pragma unroll
    for (int e = 0; e < 16; ++e) cst[e] = 0.f;

    uint32_t smem_u32;
    asm("{ .reg .u64 t; cvta.to.shared.u64 t, %1; cvt.u32.u64 %0, t; }"
        : "=r"(smem_u32) : "l"(sm));
    const uint peer = rank ^ 1;

    __syncthreads();
    asm volatile("barrier.cluster.arrive.aligned;" ::: "memory");
    asm volatile("barrier.cluster.wait.aligned;"   ::: "memory");

    const float* w1g = w1D + g * 4096;
    const float* w2g = w2D + g * 8192;
    float* tpg = tmpT + g * (64 * TPX);

    const int rb1[4] = {4*t1, 4*t1 + 2, 32 + 4*t1, 32 + 4*t1 + 2};
    const int rb2[4] = {4*t2, 4*t2 + 2, 16 + 4*t2, 16 + 4*t2 + 2};

    for (int l = 0; l < 128; ++l) {
        const float* hT = (l & 1) ? hbuf1 : hbuf0;
        float*       hN = (l & 1) ? hbuf0 : hbuf1;

        // prefetch this gate's xg values at stage2 coords (hidden behind stage1)
        float gv[8][2];
        {
            const float* xb = g_xg + ((size_t)(l * 3 + g) * 64 + n) * 4096
                              + (size_t)(32 * rank) * 64;
#pragma unroll
            for (int p = 0; p < 4; ++p) {
                int ar = rb2[p];
#pragma unroll
                for (int q = 0; q < 2; ++q) {
                    int b = 2 * s2 + q;
                    gv[2*p+q][0] = xb[ar * 64 + b];
                    gv[2*p+q][1] = xb[(ar + 1) * 64 + b];
                }
            }
        }

        // ---- stage1 ----
        {
            ull acc[8];
#pragma unroll
            for (int i = 0; i < 8; ++i) acc[i] = pack2(0.f, 0.f);
            mm82<HBX, 64>(hT, w1g, 4 * t1, 32, 4 * s1, acc);
#pragma unroll
            for (int p = 0; p < 4; ++p) {
                int jm = rb1[p];
#pragma unroll
                for (int q = 0; q < 2; ++q) {
                    float2 u = unpack2(acc[2*p+q]);
                    int a = 2 * s1 + q;
                    tpg[jm * TPX + a]       = u.x;
                    tpg[(jm + 1) * TPX + a] = u.y;
                }
            }
        }
        asm volatile("bar.sync %0, 128;" :: "r"(g + 1) : "memory");

        // ---- stage2 + sigmoid ----
        float sv[8][2];
        {
            ull acc[8];
#pragma unroll
            for (int i = 0; i < 8; ++i) acc[i] = pack2(0.f, 0.f);
            mm82<TPX, 128>(tpg, w2g, 4 * t2, 16, 4 * s2, acc);
#pragma unroll
            for (int i = 0; i < 8; ++i) {
                float2 u = unpack2(acc[i]);
                sv[i][0] = sigmoidf(u.x + gv[i][0]);
                sv[i][1] = sigmoidf(u.y + gv[i][1]);
            }
        }
        if (g < 2) {   // z (g=0), r (g=1) -> SoA buf, conflict-free
#pragma unroll
            for (int i = 0; i < 8; ++i) {
                buf[(g * 16 + 2*i)     * 128 + gt] = sv[i][0];
                buf[(g * 16 + 2*i + 1) * 128 + gt] = sv[i][1];
            }
        }
        __syncthreads();

        if (g == 2) {  // o + c owner: elementwise, write h (local/peer/out)
            float* orow = out + ((size_t)n * 128 + l) * 4096;
#pragma unroll
            for (int p = 0; p < 4; ++p) {
#pragma unroll
                for (int q = 0; q < 2; ++q) {
                    int i8 = 2*p + q;
                    int b = 2 * s2 + q;
#pragma unroll
                    for (int rr = 0; rr < 2; ++rr) {
                        int e = 2*i8 + rr;
                        int ag = 32 * rank + rb2[p] + rr;
                        float z = buf[e * 128 + gt];
                        float r = buf[(16 + e) * 128 + gt];
                        float cn = r * (cst[e] + z);     // c = r*c + z*r
                        cst[e] = cn;
                        float h = sv[i8][rr] * sigmoidf(cn);
                        hN[ag * HBX + b] = h;
                        st_cluster_f32(smem_u32 +
                            (uint32_t)(((hN - sm) + ag * HBX + b) * 4), peer, h);
                        orow[ag * 64 + b] = h;
                    }
                }
            }
        }
        asm volatile("barrier.cluster.arrive.aligned;" ::: "memory");
        asm volatile("barrier.cluster.wait.aligned;"   ::: "memory");
    }

    // epilogue: final h in hbuf0 (l=127 wrote hN=hbuf0)
    for (int e = tid; e < 2048; e += 384) {
        int al = e >> 6, b = e & 63;
        int ag = 32 * rank + al;
        out[33554432ull + (size_t)n * 4096 + ag * 64 + b] = hbuf0[ag * HBX + b];
    }
    if (g == 2) {
#pragma unroll
        for (int p = 0; p < 4; ++p)
#pragma unroll
            for (int q = 0; q < 2; ++q)
#pragma unroll
                for (int rr = 0; rr < 2; ++rr) {
                    int e = 2*(2*p+q) + rr;
                    int ag = 32 * rank + rb2[p] + rr;
                    int b = 2 * s2 + q;
                    out[33816576ull + (size_t)n * 4096 + ag * 64 + b] = cst[e];
                }
    }
}

// ============================================================================
extern "C" void kernel_launch(void* const* d_in, const int* in_sizes, int n_in,
                              void* d_out, int out_size) {
    const float* inputs = (const float*)d_in[0];
    const float* Ww1    = (const float*)d_in[1];
    const float* Ww2    = (const float*)d_in[2];
    const float* Wu1    = (const float*)d_in[3];
    const float* Wu2    = (const float*)d_in[4];
    float* out = (float*)d_out;

    const int xg_smem  = 6 * 64 * XS * sizeof(float);   // 104448 B
    const int rec_smem = 56576 * sizeof(float);         // 226304 B

    cudaFuncSetAttribute(xg_kernel,  cudaFuncAttributeMaxDynamicSharedMemorySize, xg_smem);
    cudaFuncSetAttribute(rec_kernel, cudaFuncAttributeMaxDynamicSharedMemorySize, rec_smem);

    xg_kernel<<<dim3(64, 64), 256, xg_smem>>>(inputs, Ww1, Ww2);
    rec_kernel<<<128, 384, rec_smem>>>(Wu1, Wu2, out);
}

// round 9
// speedup vs baseline: 1.0283x; 1.0283x over previous
#include <cuda_runtime.h>
#include <cuda_bf16.h>
#include <mma.h>
#include <cstdint>

using namespace nvcuda;
typedef __nv_bfloat16 bf16;
typedef unsigned int uint;

__device__ __forceinline__ float sigmoidf(float x) {
    return __fdividef(1.0f, 1.0f + __expf(-x));
}
// bf16 hi/lo split: v = h + l + O(2^-18 v)
__device__ __forceinline__ void bsplit(float v, bf16& h, bf16& l) {
    h = __float2bfloat16(v);
    l = __float2bfloat16(v - __bfloat162float(h));
}

// Warp computes a 16x32 block (two 16x16 tiles sharing the A fragment),
// 3-term bf16 split (Ah*Bh + Ah*Bl + Al*Bh), K=64, fp32 accum.
// A: row_major, ld=72, k-step = +16 elements.
// B: layout BLay, ld=72, k-step = +bstep elements.
template <typename BLay>
__device__ __forceinline__ void mm_pair(
    float* d0, float* d1, int ldd,
    const bf16* __restrict__ ah_p, const bf16* __restrict__ al_p,
    const bf16* __restrict__ bh0, const bf16* __restrict__ bl0,
    const bf16* __restrict__ bh1, const bf16* __restrict__ bl1, int bstep)
{
    wmma::fragment<wmma::accumulator, 16, 16, 16, float> c0, c1;
    wmma::fill_fragment(c0, 0.0f);
    wmma::fill_fragment(c1, 0.0f);
    wmma::fragment<wmma::matrix_a, 16, 16, 16, bf16, wmma::row_major> ah, al;
    wmma::fragment<wmma::matrix_b, 16, 16, 16, bf16, BLay> bh, bl;
#pragma unroll
    for (int k = 0; k < 4; ++k) {
        wmma::load_matrix_sync(ah, ah_p + k * 16, 72);
        wmma::load_matrix_sync(al, al_p + k * 16, 72);
        wmma::load_matrix_sync(bh, bh0 + k * bstep, 72);
        wmma::load_matrix_sync(bl, bl0 + k * bstep, 72);
        wmma::mma_sync(c0, ah, bh, c0);
        wmma::mma_sync(c0, ah, bl, c0);
        wmma::mma_sync(c0, al, bh, c0);
        wmma::load_matrix_sync(bh, bh1 + k * bstep, 72);
        wmma::load_matrix_sync(bl, bl1 + k * bstep, 72);
        wmma::mma_sync(c1, ah, bh, c1);
        wmma::mma_sync(c1, ah, bl, c1);
        wmma::mma_sync(c1, al, bh, c1);
    }
    wmma::store_matrix_sync(d0, c0, ldd, wmma::mem_row_major);
    wmma::store_matrix_sync(d1, c1, ldd, wmma::mem_row_major);
}

// xg scratch: [l][g][n][a][b]  (384 MB device .bss)
__device__ float g_xg[(size_t)3 * 128 * 64 * 64 * 64];

// ============================================================================
// Phase 1 (wmma): per (l,n): T[i,b] = sum_j X[i,j] W2[g,b,j]  (B col_major)
//                 xg[a,b]    = sum_i W1[g,a,i] T[i,b]          (B row_major)
// 256 threads = 8 warps: warp w -> m-tile (w>>1), n-half (w&1).
// ============================================================================
// smem byte offsets
#define XG_XH   0         // [64][72] bf16
#define XG_XL   9216
#define XG_W2H  18432     // [3][64][72] bf16 (rows=b)
#define XG_W2L  46080
#define XG_W1H  73728     // [3][64][72] bf16 (rows=a)
#define XG_W1L  101376
#define XG_TF   129024    // [64][68] fp32
#define XG_TH   146432    // [64][72] bf16
#define XG_TL   155648
#define XG_SMEM 164864

__global__ void __launch_bounds__(256, 1)
xg_kernel(const float* __restrict__ inputs,
          const float* __restrict__ Ww1,
          const float* __restrict__ Ww2) {
    extern __shared__ char smx[];
    bf16*  XH  = (bf16*)(smx + XG_XH);
    bf16*  XL  = (bf16*)(smx + XG_XL);
    bf16*  W2H = (bf16*)(smx + XG_W2H);
    bf16*  W2L = (bf16*)(smx + XG_W2L);
    bf16*  W1H = (bf16*)(smx + XG_W1H);
    bf16*  W1L = (bf16*)(smx + XG_W1L);
    float* TF  = (float*)(smx + XG_TF);
    bf16*  TH  = (bf16*)(smx + XG_TH);
    bf16*  TL  = (bf16*)(smx + XG_TL);

    const int tid = threadIdx.x;
    const int w = tid >> 5;
    const int mt = w >> 1, nh = w & 1;
    const int nt0 = nh * 2, nt1 = nh * 2 + 1;

    // one-time weight staging (split to hi/lo)
    for (int e = tid; e < 12288; e += 256) {
        int g = e >> 12, r = (e >> 6) & 63, c = e & 63;
        bf16 h, l;
        bsplit(Ww2[e], h, l);
        W2H[g * 4608 + r * 72 + c] = h;
        W2L[g * 4608 + r * 72 + c] = l;
        bsplit(Ww1[e], h, l);
        W1H[g * 4608 + r * 72 + c] = h;
        W1L[g * 4608 + r * 72 + c] = l;
    }

    for (int t = 0; t < 8; ++t) {
        const int flat = blockIdx.x * 8 + t;
        const int l = flat >> 6, n = flat & 63;

        const float* xsrc = inputs + ((size_t)n * 128 + l) * 4096;
        for (int e = tid; e < 4096; e += 256) {
            int i = e >> 6, j = e & 63;
            bf16 h, lo; bsplit(xsrc[e], h, lo);
            XH[i * 72 + j] = h;
            XL[i * 72 + j] = lo;
        }
        __syncthreads();   // X ready (and weights on first iter)

        for (int g = 0; g < 3; ++g) {
            // stage A: T[i][b]
            mm_pair<wmma::col_major>(
                TF + mt * 16 * 68 + nt0 * 16, TF + mt * 16 * 68 + nt1 * 16, 68,
                XH + mt * 16 * 72, XL + mt * 16 * 72,
                W2H + g * 4608 + nt0 * 16 * 72, W2L + g * 4608 + nt0 * 16 * 72,
                W2H + g * 4608 + nt1 * 16 * 72, W2L + g * 4608 + nt1 * 16 * 72, 16);
            __syncthreads();
            for (int e = tid; e < 4096; e += 256) {
                int i = e >> 6, b = e & 63;
                bf16 h, lo; bsplit(TF[i * 68 + b], h, lo);
                TH[i * 72 + b] = h;
                TL[i * 72 + b] = lo;
            }
            __syncthreads();
            // stage B: xg[a][b] -> global directly
            float* dst = g_xg + ((size_t)(l * 3 + g) * 64 + n) * 4096 + mt * 16 * 64;
            mm_pair<wmma::row_major>(
                dst + nt0 * 16, dst + nt1 * 16, 64,
                W1H + g * 4608 + mt * 16 * 72, W1L + g * 4608 + mt * 16 * 72,
                TH + nt0 * 16, TL + nt0 * 16,
                TH + nt1 * 16, TL + nt1 * 16, 16 * 72);
            __syncthreads();   // TF/TH reuse next gate; X reuse next tile
        }
    }
}

// ============================================================================
// Phase 2 (wmma): one CTA per n. Per step, per gate:
//   stage1 tmp[a][j] = sum_i W1[g,a,i] h[i][j]   (B = h, row_major)
//   stage2 hg[a][b]  = sum_j tmp[a][j] W2[g,b,j] (B = W2, col_major)
// then elementwise: z,r,o = sig(xg+hg); c = r*(c+z); h = o*sig(c).
// h kept as bf16 hi/lo in smem; c in registers (16/thread).
// ============================================================================
#define RC_HH   0         // [64][72] bf16
#define RC_HL   9216
#define RC_W1H  18432     // [3][64][72]
#define RC_W1L  46080
#define RC_W2H  73728
#define RC_W2L  101376
#define RC_TF   129024    // [64][68] fp32
#define RC_TH   146432    // [64][72] bf16
#define RC_TL   155648
#define RC_HG   164864    // [3][64][68] fp32
#define RC_SMEM 217088

__global__ void __launch_bounds__(256, 1)
rec_kernel(const float* __restrict__ Wu1,
           const float* __restrict__ Wu2,
           float* __restrict__ out) {
    extern __shared__ char smx[];
    bf16*  HH  = (bf16*)(smx + RC_HH);
    bf16*  HL  = (bf16*)(smx + RC_HL);
    bf16*  W1H = (bf16*)(smx + RC_W1H);
    bf16*  W1L = (bf16*)(smx + RC_W1L);
    bf16*  W2H = (bf16*)(smx + RC_W2H);
    bf16*  W2L = (bf16*)(smx + RC_W2L);
    float* TF  = (float*)(smx + RC_TF);
    bf16*  TH  = (bf16*)(smx + RC_TH);
    bf16*  TL  = (bf16*)(smx + RC_TL);
    float* HG  = (float*)(smx + RC_HG);

    const int n = blockIdx.x;
    const int tid = threadIdx.x;
    const int w = tid >> 5;
    const int mt = w >> 1, nh = w & 1;
    const int nt0 = nh * 2, nt1 = nh * 2 + 1;
    // elementwise ownership: row a_e, 16 cols from b0
    const int a_e = tid >> 2, b0 = (tid & 3) << 4;

    for (int e = tid; e < 12288; e += 256) {
        int g = e >> 12, r = (e >> 6) & 63, c = e & 63;
        bf16 h, l;
        bsplit(Wu1[e], h, l);
        W1H[g * 4608 + r * 72 + c] = h;
        W1L[g * 4608 + r * 72 + c] = l;
        bsplit(Wu2[e], h, l);
        W2H[g * 4608 + r * 72 + c] = h;
        W2L[g * 4608 + r * 72 + c] = l;
    }
    for (int e = tid; e < 4608; e += 256) {
        HH[e] = __float2bfloat16(0.f);
        HL[e] = __float2bfloat16(0.f);
    }
    float cst[16];
#pragma unroll
    for (int e = 0; e < 16; ++e) cst[e] = 0.f;
    __syncthreads();

    for (int l = 0; l < 128; ++l) {
        for (int g = 0; g < 3; ++g) {
            // stage1: tmp[a][j] (A = W1 static, B = h row_major)
            mm_pair<wmma::row_major>(
                TF + mt * 16 * 68 + nt0 * 16, TF + mt * 16 * 68 + nt1 * 16, 68,
                W1H + g * 4608 + mt * 16 * 72, W1L + g * 4608 + mt * 16 * 72,
                HH + nt0 * 16, HL + nt0 * 16,
                HH + nt1 * 16, HL + nt1 * 16, 16 * 72);
            __syncthreads();
            for (int e = tid; e < 4096; e += 256) {
                int a = e >> 6, j = e & 63;
                bf16 h, lo; bsplit(TF[a * 68 + j], h, lo);
                TH[a * 72 + j] = h;
                TL[a * 72 + j] = lo;
            }
            __syncthreads();
            // stage2: hg[a][b] (A = tmp, B = W2 col_major) -> HG[g]
            mm_pair<wmma::col_major>(
                HG + g * 4352 + mt * 16 * 68 + nt0 * 16,
                HG + g * 4352 + mt * 16 * 68 + nt1 * 16, 68,
                TH + mt * 16 * 72, TL + mt * 16 * 72,
                W2H + g * 4608 + nt0 * 16 * 72, W2L + g * 4608 + nt0 * 16 * 72,
                W2H + g * 4608 + nt1 * 16 * 72, W2L + g * 4608 + nt1 * 16 * 72, 16);
            __syncthreads();
        }

        // elementwise update; write outs + new h (fp32->out, split->smem)
        {
            const float* xgp = g_xg + ((size_t)(l * 3) * 64 + n) * 4096 + a_e * 64 + b0;
            float* orow = out + ((size_t)n * 128 + l) * 4096 + a_e * 64 + b0;
            const float* hgp = HG + a_e * 68 + b0;
#pragma unroll
            for (int q = 0; q < 4; ++q) {
                float4 xz = *(const float4*)(xgp + q * 4);
                float4 xr = *(const float4*)(xgp + 262144 + q * 4);
                float4 xo = *(const float4*)(xgp + 524288 + q * 4);
                float4 gz = *(const float4*)(hgp + q * 4);
                float4 gr = *(const float4*)(hgp + 4352 + q * 4);
                float4 go = *(const float4*)(hgp + 8704 + q * 4);
                float zz[4] = {xz.x + gz.x, xz.y + gz.y, xz.z + gz.z, xz.w + gz.w};
                float rr[4] = {xr.x + gr.x, xr.y + gr.y, xr.z + gr.z, xr.w + gr.w};
                float oo[4] = {xo.x + go.x, xo.y + go.y, xo.z + go.z, xo.w + go.w};
                float hv[4];
#pragma unroll
                for (int m = 0; m < 4; ++m) {
                    float z = sigmoidf(zz[m]);
                    float r = sigmoidf(rr[m]);
                    float o = sigmoidf(oo[m]);
                    int e = q * 4 + m;
                    float cn = r * (cst[e] + z);   // c = r*c + z*r
                    cst[e] = cn;
                    hv[m] = o * sigmoidf(cn);      // h = o*sig(c)
                }
                *(float4*)(orow + q * 4) = make_float4(hv[0], hv[1], hv[2], hv[3]);
                // split new h into smem state
                bf16 h0, l0, h1, l1;
                __nv_bfloat162* HH2 = (__nv_bfloat162*)(HH + a_e * 72 + b0 + q * 4);
                __nv_bfloat162* HL2 = (__nv_bfloat162*)(HL + a_e * 72 + b0 + q * 4);
                bsplit(hv[0], h0, l0); bsplit(hv[1], h1, l1);
                HH2[0] = __nv_bfloat162(h0, h1);
                HL2[0] = __nv_bfloat162(l0, l1);
                bsplit(hv[2], h0, l0); bsplit(hv[3], h1, l1);
                HH2[1] = __nv_bfloat162(h0, h1);
                HL2[1] = __nv_bfloat162(l0, l1);
            }
        }
        __syncthreads();   // h state + HG consumption complete
    }

    // epilogue: h_last = outs[:,127] (copy); c_last from registers.
    {
        const float* hsrc = out + ((size_t)n * 128 + 127) * 4096;
        float* hl = out + 33554432ull + (size_t)n * 4096;
        for (int e = tid; e < 4096; e += 256) hl[e] = hsrc[e];
        float* cl = out + 33816576ull + (size_t)n * 4096 + a_e * 64 + b0;
#pragma unroll
        for (int q = 0; q < 4; ++q)
            *(float4*)(cl + q * 4) =
                make_float4(cst[q*4+0], cst[q*4+1], cst[q*4+2], cst[q*4+3]);
    }
}

// ============================================================================
extern "C" void kernel_launch(void* const* d_in, const int* in_sizes, int n_in,
                              void* d_out, int out_size) {
    const float* inputs = (const float*)d_in[0];   // (64,128,64,64)
    const float* Ww1    = (const float*)d_in[1];   // (4,64,64) — g<3 used
    const float* Ww2    = (const float*)d_in[2];
    const float* Wu1    = (const float*)d_in[3];
    const float* Wu2    = (const float*)d_in[4];
    float* out = (float*)d_out;

    cudaFuncSetAttribute(xg_kernel,  cudaFuncAttributeMaxDynamicSharedMemorySize, XG_SMEM);
    cudaFuncSetAttribute(rec_kernel, cudaFuncAttributeMaxDynamicSharedMemorySize, RC_SMEM);

    xg_kernel<<<1024, 256, XG_SMEM>>>(inputs, Ww1, Ww2);
    rec_kernel<<<64, 256, RC_SMEM>>>(Wu1, Wu2, out);
}